// round 15
// baseline (speedup 1.0000x reference)
#include <cuda_runtime.h>
#include <cstdint>

// Self-attention N=2, S=2048, E=1024, H=16, D=64, fp32 I/O.  sm_100 target.
// R15: softmax scale folded into Q at projection (QK^T emits pre-scaled
// logits; softmax = pack->ex2->maskmul, no FMULs); outproj retiled to
// 128x64 (32 acc regs -> occ 3, frees registers for LDSM/mma pipelining).

#define NBATCH 2
#define SEQL   2048
#define NHEADS 16
#define HDIM   64
#define EMBED  1024
#define NS     (NBATCH * SEQL)
#define ROWS_H (NS * NHEADS)
#define HELEMS (NBATCH * NHEADS * SEQL * HDIM)

__device__ unsigned short g_Qp[HELEMS];        // fp16 bits, pre-scaled by SC2
__device__ unsigned short g_Kp[HELEMS];
__device__ unsigned short g_Vp[HELEMS];
__device__ unsigned short g_Ao[NS * EMBED];    // fp16 bits
__device__ unsigned short g_Wo16[EMBED * EMBED];

// ---------------------------------------------------------------------------
// helpers
// ---------------------------------------------------------------------------
__device__ __forceinline__ uint32_t smem_u32(const void* p) {
    uint32_t a;
    asm("{ .reg .u64 t; cvta.to.shared.u64 t, %1; cvt.u32.u64 %0, t; }"
        : "=r"(a) : "l"(p));
    return a;
}
__device__ __forceinline__ uint32_t f2tf32(float x) {
    uint32_t r;
    asm("cvt.rna.tf32.f32 %0, %1;" : "=r"(r) : "f"(x));
    return r;
}
__device__ __forceinline__ uint32_t packf16(float lo, float hi) {
    uint32_t r;   // first PTX src = high half
    asm("cvt.rn.f16x2.f32 %0, %1, %2;" : "=r"(r) : "f"(hi), "f"(lo));
    return r;
}
__device__ __forceinline__ uint32_t ex2h2(uint32_t a) {
    uint32_t r;
    asm("ex2.approx.f16x2 %0, %1;" : "=r"(r) : "r"(a));
    return r;
}
__device__ __forceinline__ uint32_t hmul2(uint32_t a, uint32_t b) {
    uint32_t r;
    asm("mul.rn.f16x2 %0, %1, %2;" : "=r"(r) : "r"(a), "r"(b));
    return r;
}
// tf32 m16n8k8 (proj)
__device__ __forceinline__ void mma8(float* c, const uint32_t* a, const uint32_t* b) {
    asm volatile(
        "mma.sync.aligned.m16n8k8.row.col.f32.tf32.tf32.f32 "
        "{%0,%1,%2,%3}, {%4,%5,%6,%7}, {%8,%9}, {%0,%1,%2,%3};"
        : "+f"(c[0]), "+f"(c[1]), "+f"(c[2]), "+f"(c[3])
        : "r"(a[0]), "r"(a[1]), "r"(a[2]), "r"(a[3]), "r"(b[0]), "r"(b[1]));
}
// fp16 m16n8k16 (attention / outproj)
__device__ __forceinline__ void mma16(float* c, const uint32_t* a, const uint32_t* b) {
    asm volatile(
        "mma.sync.aligned.m16n8k16.row.col.f32.f16.f16.f32 "
        "{%0,%1,%2,%3}, {%4,%5,%6,%7}, {%8,%9}, {%0,%1,%2,%3};"
        : "+f"(c[0]), "+f"(c[1]), "+f"(c[2]), "+f"(c[3])
        : "r"(a[0]), "r"(a[1]), "r"(a[2]), "r"(a[3]), "r"(b[0]), "r"(b[1]));
}
#define LDSM_X4(r, addr) \
    asm volatile("ldmatrix.sync.aligned.m8n8.x4.shared.b16 {%0,%1,%2,%3}, [%4];" \
        : "=r"((r)[0]), "=r"((r)[1]), "=r"((r)[2]), "=r"((r)[3]) : "r"(addr))
#define LDSM_X4T(r, addr) \
    asm volatile("ldmatrix.sync.aligned.m8n8.x4.trans.shared.b16 {%0,%1,%2,%3}, [%4];" \
        : "=r"((r)[0]), "=r"((r)[1]), "=r"((r)[2]), "=r"((r)[3]) : "r"(addr))

#define CP_ASYNC16(dst, src) \
    asm volatile("cp.async.cg.shared.global [%0], [%1], 16;" \
                 :: "r"((uint32_t)(dst)), "l"(src))
#define CP_COMMIT() asm volatile("cp.async.commit_group;" ::: "memory")
#define CP_WAIT0()  asm volatile("cp.async.wait_group 0;" ::: "memory")

#define SC2 0.045084220f   // log2(e)/32 : exp(s/32) = 2^(q_scaled . k)
#define ONEX2 0x3C003C00u  // fp16x2 (1.0, 1.0)
#define ROWB 144           // padded row bytes (72 fp16) for CF ldmatrix

// ---------------------------------------------------------------------------
// 0) Wo fp32 -> fp16 (one-shot, memory-bound)
// ---------------------------------------------------------------------------
__global__ __launch_bounds__(256) void cvt_wo(const float* __restrict__ Wo)
{
    int idx = blockIdx.x * 256 + threadIdx.x;          // float4 index
    float4 v = reinterpret_cast<const float4*>(Wo)[idx];
    *reinterpret_cast<uint2*>(g_Wo16 + (size_t)idx * 4) =
        make_uint2(packf16(v.x, v.y), packf16(v.z, v.w));
}

// ---------------------------------------------------------------------------
// 1) projections via tf32 mma; OUTPUT = packed fp16. Q scaled by SC2.
// smem (dynamic): Xs[128][68] u32 @0 (34816), Ws[64][68] @34816 (17408).
// ---------------------------------------------------------------------------
#define PX 0
#define PW 34816
#define PROJ_SMEM 52224

__global__ __launch_bounds__(256) void proj_mma(
    const float* __restrict__ qin, const float* __restrict__ kin,
    const float* __restrict__ vin,
    const float* __restrict__ Wq, const float* __restrict__ Wk,
    const float* __restrict__ Wv)
{
    extern __shared__ char smem[];
    uint32_t* Xs = reinterpret_cast<uint32_t*>(smem + PX);
    uint32_t* Ws = reinterpret_cast<uint32_t*>(smem + PW);

    const float* src; const float* W; unsigned short* dst;
    if (blockIdx.y == 0)      { src = qin; W = Wq; dst = g_Qp; }
    else if (blockIdx.y == 1) { src = kin; W = Wk; dst = g_Kp; }
    else                      { src = vin; W = Wv; dst = g_Vp; }
    const float oscale = (blockIdx.y == 0) ? SC2 : 1.0f;

    const int t = threadIdx.x, lane = t & 31, warp = t >> 5;
    const int wy = warp >> 1, wx = warp & 1;
    const int lr = lane >> 2, lc = lane & 3;

    const float4* sv = reinterpret_cast<const float4*>(src + (size_t)blockIdx.x * 8192);
    const float4* wv = reinterpret_cast<const float4*>(W);
#pragma unroll
    for (int i = 0; i < 8; i++) {
        int idx = i * 256 + t;
        float4 v = sv[idx];
        int r = idx >> 4, c = (idx & 15) * 4;
        Xs[r*68+c+0] = f2tf32(v.x); Xs[r*68+c+1] = f2tf32(v.y);
        Xs[r*68+c+2] = f2tf32(v.z); Xs[r*68+c+3] = f2tf32(v.w);
    }
#pragma unroll
    for (int i = 0; i < 4; i++) {
        int idx = i * 256 + t;
        float4 v = wv[idx];
        int r = idx >> 4, c = (idx & 15) * 4;
        Ws[r*68+c+0] = f2tf32(v.x); Ws[r*68+c+1] = f2tf32(v.y);
        Ws[r*68+c+2] = f2tf32(v.z); Ws[r*68+c+3] = f2tf32(v.w);
    }
    __syncthreads();

    float acc[2][4][4];
#pragma unroll
    for (int mt = 0; mt < 2; mt++)
#pragma unroll
        for (int nt = 0; nt < 4; nt++)
#pragma unroll
            for (int e = 0; e < 4; e++) acc[mt][nt][e] = 0.f;

#pragma unroll
    for (int kk = 0; kk < 8; kk++) {
        int k0 = kk * 8 + lc;
        uint32_t af[2][4], bf[4][2];
#pragma unroll
        for (int mt = 0; mt < 2; mt++) {
            int r = 32 * wy + 16 * mt + lr;
            af[mt][0] = Xs[r * 68 + k0];
            af[mt][1] = Xs[(r + 8) * 68 + k0];
            af[mt][2] = Xs[r * 68 + k0 + 4];
            af[mt][3] = Xs[(r + 8) * 68 + k0 + 4];
        }
#pragma unroll
        for (int nt = 0; nt < 4; nt++) {
            int nr = 32 * wx + 8 * nt + lr;
            bf[nt][0] = Ws[nr * 68 + k0];
            bf[nt][1] = Ws[nr * 68 + k0 + 4];
        }
#pragma unroll
        for (int mt = 0; mt < 2; mt++)
#pragma unroll
            for (int nt = 0; nt < 4; nt++)
                mma8(acc[mt][nt], af[mt], bf[nt]);
    }

#pragma unroll
    for (int mt = 0; mt < 2; mt++) {
#pragma unroll
        for (int half = 0; half < 2; half++) {
            int r = 32 * wy + 16 * mt + 8 * half + lr;
            int g = blockIdx.x * 128 + r;
            int n = g >> 15;
            int s = (g >> 4) & (SEQL - 1);
            int h = g & (NHEADS - 1);
            unsigned short* ob = dst + ((size_t)((n * NHEADS + h) * SEQL + s)) * HDIM;
#pragma unroll
            for (int nt = 0; nt < 4; nt++) {
                int c = 32 * wx + 8 * nt + 2 * lc;
                *reinterpret_cast<uint32_t*>(ob + c) =
                    packf16(acc[mt][nt][half * 2 + 0] * oscale,
                            acc[mt][nt][half * 2 + 1] * oscale);
            }
        }
    }
}

// ---------------------------------------------------------------------------
// 2) attention: fp16 mma, register P, f16x2 ex2 softmax (scale pre-folded
// into Q), ones-mma row sums. Block = 128 q-rows; warp owns 16 rows x all
// 64 keys. One barrier per chunk; K/V double-buffer.
// smem (ROWB=144): Qs@0, Ks0@18432 Ks1@27648, Vs0@36864 Vs1@46080,
// msk[2][64]@55296.
// ---------------------------------------------------------------------------
#define AQ   0
#define AK0  18432
#define AK1  27648
#define AV0  36864
#define AV1  46080
#define AMSK 55296
#define ATT_SMEM 55808

__global__ __launch_bounds__(256, 2) void attn_mma(const int* __restrict__ mask)
{
    extern __shared__ char smem[];
    const uint32_t sb = smem_u32(smem);
    int* msk = reinterpret_cast<int*>(smem + AMSK);

    const int tid = threadIdx.x, lane = tid & 31, warp = tid >> 5;
    const int qb = blockIdx.x, h = blockIdx.y, n = blockIdx.z;
    const int lr = lane >> 2, lc = lane & 3;
    const int lr8 = lane & 7, g1 = (lane >> 3) & 1, g2 = (lane >> 4) & 1;

    const size_t hb = ((size_t)(n * NHEADS + h)) * SEQL * HDIM;
    const unsigned short* Qg  = g_Qp + hb + (size_t)qb * 128 * 64;
    const unsigned short* Kg0 = g_Kp + hb;
    const unsigned short* Vg0 = g_Vp + hb;
    const int* mg = mask + n * SEQL;

    const uint32_t q_off = (uint32_t)((16 * warp + 8 * g1 + lr8) * ROWB + g2 * 16);
    const uint32_t k_off = (uint32_t)((8 * g2 + lr8) * ROWB + g1 * 16);
    const uint32_t v_off = (uint32_t)((8 * g1 + lr8) * ROWB + g2 * 16);

    // prologue: Q tile + chunk0 K/V + mask0, one group
#pragma unroll
    for (int i = 0; i < 4; i++) {
        int idx = i * 256 + tid;
        int r = idx >> 3, cc = idx & 7;
        CP_ASYNC16(sb + AQ + (uint32_t)(r * ROWB + cc * 16), Qg + r * 64 + cc * 8);
    }
#pragma unroll
    for (int i = 0; i < 2; i++) {
        int idx = i * 256 + tid;
        int r = idx >> 3, cc = idx & 7;
        CP_ASYNC16(sb + AK0 + (uint32_t)(r * ROWB + cc * 16), Kg0 + r * 64 + cc * 8);
        CP_ASYNC16(sb + AV0 + (uint32_t)(r * ROWB + cc * 16), Vg0 + r * 64 + cc * 8);
    }
    if (tid < 16) CP_ASYNC16(sb + AMSK + tid * 16, mg + tid * 4);
    CP_COMMIT();

    float oacc[8][4];
    float lacc[4];     // ones-mma row-sum accumulator: [0]=row lr, [2]=row lr+8
#pragma unroll
    for (int j = 0; j < 8; j++)
#pragma unroll
        for (int e = 0; e < 4; e++) oacc[j][e] = 0.f;
#pragma unroll
    for (int e = 0; e < 4; e++) lacc[e] = 0.f;
    uint32_t qa[4][4];
    const uint32_t onesb[2] = {ONEX2, ONEX2};

    for (int kb = 0; kb < SEQL / 64; kb++) {
        CP_WAIT0();
        __syncthreads();   // chunk kb visible; all warps done with old buffer

        if (kb == 0) {
#pragma unroll
            for (int ks = 0; ks < 4; ks++)
                LDSM_X4(qa[ks], sb + AQ + q_off + ks * 32);
        }
        // prefetch chunk kb+1 into the other buffer
        if (kb < SEQL / 64 - 1) {
            const unsigned short* Kg = Kg0 + (size_t)(kb + 1) * 4096;
            const unsigned short* Vg = Vg0 + (size_t)(kb + 1) * 4096;
            uint32_t kbn = sb + (((kb + 1) & 1) ? AK1 : AK0);
            uint32_t vbn = sb + (((kb + 1) & 1) ? AV1 : AV0);
#pragma unroll
            for (int i = 0; i < 2; i++) {
                int idx = i * 256 + tid;
                int r = idx >> 3, cc = idx & 7;
                CP_ASYNC16(kbn + (uint32_t)(r * ROWB + cc * 16), Kg + r * 64 + cc * 8);
                CP_ASYNC16(vbn + (uint32_t)(r * ROWB + cc * 16), Vg + r * 64 + cc * 8);
            }
            if (tid < 16)
                CP_ASYNC16(sb + AMSK + ((kb + 1) & 1) * 256 + tid * 16,
                           mg + (kb + 1) * 64 + tid * 4);
            CP_COMMIT();
        }

        const uint32_t kbase = sb + ((kb & 1) ? AK1 : AK0);
        const uint32_t vbase = sb + ((kb & 1) ? AV1 : AV0);
        const int mb = (kb & 1) * 64;

        // S_scaled = (Q*SC2) K^T
        float sacc[8][4];
#pragma unroll
        for (int j = 0; j < 8; j++)
#pragma unroll
            for (int e = 0; e < 4; e++) sacc[j][e] = 0.f;

#pragma unroll
        for (int ks = 0; ks < 4; ks++) {
            uint32_t kf[4][4];
#pragma unroll
            for (int t = 0; t < 4; t++)
                LDSM_X4(kf[t], kbase + k_off + (uint32_t)(t * 16 * ROWB) + ks * 32);
#pragma unroll
            for (int t = 0; t < 4; t++) {
                mma16(sacc[2 * t + 0], qa[ks], &kf[t][0]);
                mma16(sacc[2 * t + 1], qa[ks], &kf[t][2]);
            }
        }

        // softmax: p = 2^s_scaled via ex2.approx.f16x2; mask via f16x2 mul
        uint32_t pa[16];
#pragma unroll
        for (int t = 0; t < 8; t++) {
            int c = 8 * t + 2 * lc;
            uint32_t mm = (msk[mb + c] ? 0x3C00u : 0u)
                        | (msk[mb + c + 1] ? 0x3C000000u : 0u);
            uint32_t e01 = packf16(sacc[t][0], sacc[t][1]);
            uint32_t e23 = packf16(sacc[t][2], sacc[t][3]);
            pa[(t >> 1) * 4 + (t & 1) * 2 + 0] = hmul2(ex2h2(e01), mm);
            pa[(t >> 1) * 4 + (t & 1) * 2 + 1] = hmul2(ex2h2(e23), mm);
        }

        // O += P V ; row sums += P @ ones (one extra n=8 mma per ks)
#pragma unroll
        for (int ks = 0; ks < 4; ks++) {
            uint32_t vf[4][4];
#pragma unroll
            for (int t = 0; t < 4; t++)
                LDSM_X4T(vf[t], vbase + v_off + (uint32_t)(ks * 16 * ROWB) + t * 32);
#pragma unroll
            for (int t = 0; t < 4; t++) {
                mma16(oacc[2 * t + 0], &pa[ks * 4], &vf[t][0]);
                mma16(oacc[2 * t + 1], &pa[ks * 4], &vf[t][2]);
            }
            mma16(lacc, &pa[ks * 4], onesb);
        }
    }

    float inv0 = 1.f / lacc[0], inv1 = 1.f / lacc[2];

    // normalize + write Ao fp16
    int r0 = qb * 128 + 16 * warp + lr;
    unsigned short* b0 = g_Ao + ((size_t)(n * SEQL + r0)) * EMBED + h * HDIM;
    unsigned short* b1 = g_Ao + ((size_t)(n * SEQL + r0 + 8)) * EMBED + h * HDIM;
#pragma unroll
    for (int j = 0; j < 8; j++) {
        int c = 8 * j + 2 * lc;
        *reinterpret_cast<uint32_t*>(b0 + c) =
            packf16(oacc[j][0] * inv0, oacc[j][1] * inv0);
        *reinterpret_cast<uint32_t*>(b1 + c) =
            packf16(oacc[j][2] * inv1, oacc[j][3] * inv1);
    }
}

// ---------------------------------------------------------------------------
// 3) out = Ao @ Wo^T + bo : fp16 mma + ldmatrix, 128x64 tile (warp = 16
// rows x all 64 cols; acc 32 regs -> occ 3), k-chunk 64 double-buffered.
// smem: A0@0 (18432) A1@18432, B0@36864 (9216) B1@46080, bias @55296 (256B).
// ---------------------------------------------------------------------------
#define OA0 0
#define OA1 18432
#define OB0 36864
#define OB1 46080
#define OBI 55296
#define OP_SMEM 55552

__global__ __launch_bounds__(256, 3) void outproj_mma(
    const float* __restrict__ bo, float* __restrict__ out)
{
    extern __shared__ char smem[];
    const uint32_t sb = smem_u32(smem);
    float* sbo = reinterpret_cast<float*>(smem + OBI);

    const int tid = threadIdx.x, lane = tid & 31, warp = tid >> 5;
    const int lr = lane >> 2, lc = lane & 3;
    const int lr8 = lane & 7, g1 = (lane >> 3) & 1, g2 = (lane >> 4) & 1;
    const int cb = blockIdx.x, rb = blockIdx.y;

    if (tid < 64) sbo[tid] = bo[cb * 64 + tid];

    const unsigned short* Ag = g_Ao + (size_t)rb * 128 * EMBED;
    const unsigned short* Bg = g_Wo16 + (size_t)cb * 64 * EMBED;

    const uint32_t a_off = (uint32_t)((16 * warp + 8 * g1 + lr8) * ROWB + g2 * 16);
    const uint32_t b_off = (uint32_t)((8 * g2 + lr8) * ROWB + g1 * 16);

    // prologue: chunk 0 into buffer 0 (A: 4/thr, B: 2/thr)
#pragma unroll
    for (int i = 0; i < 4; i++) {
        int idx = i * 256 + tid;
        int r = idx >> 3, cc = idx & 7;
        CP_ASYNC16(sb + OA0 + (uint32_t)(r * ROWB + cc * 16),
                   Ag + (size_t)r * EMBED + cc * 8);
    }
#pragma unroll
    for (int i = 0; i < 2; i++) {
        int idx = i * 256 + tid;
        int r = idx >> 3, cc = idx & 7;
        CP_ASYNC16(sb + OB0 + (uint32_t)(r * ROWB + cc * 16),
                   Bg + (size_t)r * EMBED + cc * 8);
    }
    CP_COMMIT();

    float acc[8][4];
#pragma unroll
    for (int nt = 0; nt < 8; nt++)
#pragma unroll
        for (int e = 0; e < 4; e++) acc[nt][e] = 0.f;

    for (int kt = 0; kt < EMBED / 64; kt++) {
        CP_WAIT0();          // chunk kt landed
        __syncthreads();     // everyone done with the other buffer

        if (kt < EMBED / 64 - 1) {       // prefetch kt+1, overlaps mma below
            int koff = (kt + 1) * 64;
            uint32_t oa = ((kt + 1) & 1) ? OA1 : OA0;
            uint32_t ob = ((kt + 1) & 1) ? OB1 : OB0;
#pragma unroll
            for (int i = 0; i < 4; i++) {
                int idx = i * 256 + tid;
                int r = idx >> 3, cc = idx & 7;
                CP_ASYNC16(sb + oa + (uint32_t)(r * ROWB + cc * 16),
                           Ag + (size_t)r * EMBED + koff + cc * 8);
            }
#pragma unroll
            for (int i = 0; i < 2; i++) {
                int idx = i * 256 + tid;
                int r = idx >> 3, cc = idx & 7;
                CP_ASYNC16(sb + ob + (uint32_t)(r * ROWB + cc * 16),
                           Bg + (size_t)r * EMBED + koff + cc * 8);
            }
            CP_COMMIT();
        }

        const uint32_t abase = sb + ((kt & 1) ? OA1 : OA0);
        const uint32_t bbase = sb + ((kt & 1) ? OB1 : OB0);

#pragma unroll
        for (int ks = 0; ks < 4; ks++) {
            uint32_t af[4], bfr[4][4];
            LDSM_X4(af, abase + a_off + ks * 32);
#pragma unroll
            for (int t = 0; t < 4; t++)
                LDSM_X4(bfr[t], bbase + b_off +
                               (uint32_t)(16 * t * ROWB) + ks * 32);
#pragma unroll
            for (int t = 0; t < 4; t++) {
                mma16(acc[2 * t + 0], af, &bfr[t][0]);
                mma16(acc[2 * t + 1], af, &bfr[t][2]);
            }
        }
    }

    int r0 = rb * 128 + 16 * warp + lr;
    float* o0 = out + (size_t)r0 * EMBED + cb * 64;
    float* o1 = out + (size_t)(r0 + 8) * EMBED + cb * 64;
#pragma unroll
    for (int nt = 0; nt < 8; nt++) {
        int c = 8 * nt + 2 * lc;
        *reinterpret_cast<float2*>(o0 + c) =
            make_float2(acc[nt][0] + sbo[c], acc[nt][1] + sbo[c + 1]);
        *reinterpret_cast<float2*>(o1 + c) =
            make_float2(acc[nt][2] + sbo[c], acc[nt][3] + sbo[c + 1]);
    }
}

// ---------------------------------------------------------------------------
extern "C" void kernel_launch(void* const* d_in, const int* in_sizes, int n_in,
                              void* d_out, int out_size)
{
    (void)in_sizes; (void)n_in; (void)out_size;
    const float* vals = (const float*)d_in[0];
    const float* keys = (const float*)d_in[1];
    const float* qry  = (const float*)d_in[2];
    const int*   mask = (const int*)d_in[3];
    const float* Wv   = (const float*)d_in[4];
    const float* Wk   = (const float*)d_in[5];
    const float* Wq   = (const float*)d_in[6];
    const float* Wo   = (const float*)d_in[7];
    const float* bo   = (const float*)d_in[8];
    float* out = (float*)d_out;

    cudaFuncSetAttribute(proj_mma, cudaFuncAttributeMaxDynamicSharedMemorySize, PROJ_SMEM);
    cudaFuncSetAttribute(attn_mma, cudaFuncAttributeMaxDynamicSharedMemorySize, ATT_SMEM);
    cudaFuncSetAttribute(outproj_mma, cudaFuncAttributeMaxDynamicSharedMemorySize, OP_SMEM);

    cvt_wo<<<EMBED * EMBED / 1024, 256>>>(Wo);
    proj_mma<<<dim3(ROWS_H / 128, 3), 256, PROJ_SMEM>>>(qry, keys, vals, Wq, Wk, Wv);
    attn_mma<<<dim3(SEQL / 128, NHEADS, NBATCH), 256, ATT_SMEM>>>(mask);
    outproj_mma<<<dim3(EMBED / 64, NS / 128), 256, OP_SMEM>>>(bo, out);
}

// round 16
// speedup vs baseline: 1.0433x; 1.0433x over previous
#include <cuda_runtime.h>
#include <cstdint>

// Self-attention N=2, S=2048, E=1024, H=16, D=64, fp32 I/O.  sm_100 target.
// R16: R15's proj/attn (softmax scale folded into Q; measured -3us) with
// outproj reverted to R14's 128x128 double-buffered tile (R15's 128x64
// retile doubled A-tile L2 traffic and regressed 36.4 -> 45.8us).

#define NBATCH 2
#define SEQL   2048
#define NHEADS 16
#define HDIM   64
#define EMBED  1024
#define NS     (NBATCH * SEQL)
#define ROWS_H (NS * NHEADS)
#define HELEMS (NBATCH * NHEADS * SEQL * HDIM)

__device__ unsigned short g_Qp[HELEMS];        // fp16 bits, pre-scaled by SC2
__device__ unsigned short g_Kp[HELEMS];
__device__ unsigned short g_Vp[HELEMS];
__device__ unsigned short g_Ao[NS * EMBED];    // fp16 bits
__device__ unsigned short g_Wo16[EMBED * EMBED];

// ---------------------------------------------------------------------------
// helpers
// ---------------------------------------------------------------------------
__device__ __forceinline__ uint32_t smem_u32(const void* p) {
    uint32_t a;
    asm("{ .reg .u64 t; cvta.to.shared.u64 t, %1; cvt.u32.u64 %0, t; }"
        : "=r"(a) : "l"(p));
    return a;
}
__device__ __forceinline__ uint32_t f2tf32(float x) {
    uint32_t r;
    asm("cvt.rna.tf32.f32 %0, %1;" : "=r"(r) : "f"(x));
    return r;
}
__device__ __forceinline__ uint32_t packf16(float lo, float hi) {
    uint32_t r;   // first PTX src = high half
    asm("cvt.rn.f16x2.f32 %0, %1, %2;" : "=r"(r) : "f"(hi), "f"(lo));
    return r;
}
__device__ __forceinline__ uint32_t ex2h2(uint32_t a) {
    uint32_t r;
    asm("ex2.approx.f16x2 %0, %1;" : "=r"(r) : "r"(a));
    return r;
}
__device__ __forceinline__ uint32_t hmul2(uint32_t a, uint32_t b) {
    uint32_t r;
    asm("mul.rn.f16x2 %0, %1, %2;" : "=r"(r) : "r"(a), "r"(b));
    return r;
}
// tf32 m16n8k8 (proj)
__device__ __forceinline__ void mma8(float* c, const uint32_t* a, const uint32_t* b) {
    asm volatile(
        "mma.sync.aligned.m16n8k8.row.col.f32.tf32.tf32.f32 "
        "{%0,%1,%2,%3}, {%4,%5,%6,%7}, {%8,%9}, {%0,%1,%2,%3};"
        : "+f"(c[0]), "+f"(c[1]), "+f"(c[2]), "+f"(c[3])
        : "r"(a[0]), "r"(a[1]), "r"(a[2]), "r"(a[3]), "r"(b[0]), "r"(b[1]));
}
// fp16 m16n8k16 (attention / outproj)
__device__ __forceinline__ void mma16(float* c, const uint32_t* a, const uint32_t* b) {
    asm volatile(
        "mma.sync.aligned.m16n8k16.row.col.f32.f16.f16.f32 "
        "{%0,%1,%2,%3}, {%4,%5,%6,%7}, {%8,%9}, {%0,%1,%2,%3};"
        : "+f"(c[0]), "+f"(c[1]), "+f"(c[2]), "+f"(c[3])
        : "r"(a[0]), "r"(a[1]), "r"(a[2]), "r"(a[3]), "r"(b[0]), "r"(b[1]));
}
#define LDSM_X4(r, addr) \
    asm volatile("ldmatrix.sync.aligned.m8n8.x4.shared.b16 {%0,%1,%2,%3}, [%4];" \
        : "=r"((r)[0]), "=r"((r)[1]), "=r"((r)[2]), "=r"((r)[3]) : "r"(addr))
#define LDSM_X4T(r, addr) \
    asm volatile("ldmatrix.sync.aligned.m8n8.x4.trans.shared.b16 {%0,%1,%2,%3}, [%4];" \
        : "=r"((r)[0]), "=r"((r)[1]), "=r"((r)[2]), "=r"((r)[3]) : "r"(addr))

#define CP_ASYNC16(dst, src) \
    asm volatile("cp.async.cg.shared.global [%0], [%1], 16;" \
                 :: "r"((uint32_t)(dst)), "l"(src))
#define CP_COMMIT() asm volatile("cp.async.commit_group;" ::: "memory")
#define CP_WAIT0()  asm volatile("cp.async.wait_group 0;" ::: "memory")

#define SC2 0.045084220f   // log2(e)/32 : exp(s/32) = 2^(q_scaled . k)
#define ONEX2 0x3C003C00u  // fp16x2 (1.0, 1.0)
#define ROWB 144           // padded row bytes (72 fp16) for CF ldmatrix

// ---------------------------------------------------------------------------
// 0) Wo fp32 -> fp16 (one-shot, memory-bound)
// ---------------------------------------------------------------------------
__global__ __launch_bounds__(256) void cvt_wo(const float* __restrict__ Wo)
{
    int idx = blockIdx.x * 256 + threadIdx.x;          // float4 index
    float4 v = reinterpret_cast<const float4*>(Wo)[idx];
    *reinterpret_cast<uint2*>(g_Wo16 + (size_t)idx * 4) =
        make_uint2(packf16(v.x, v.y), packf16(v.z, v.w));
}

// ---------------------------------------------------------------------------
// 1) projections via tf32 mma; OUTPUT = packed fp16. Q scaled by SC2.
// smem (dynamic): Xs[128][68] u32 @0 (34816), Ws[64][68] @34816 (17408).
// ---------------------------------------------------------------------------
#define PX 0
#define PW 34816
#define PROJ_SMEM 52224

__global__ __launch_bounds__(256) void proj_mma(
    const float* __restrict__ qin, const float* __restrict__ kin,
    const float* __restrict__ vin,
    const float* __restrict__ Wq, const float* __restrict__ Wk,
    const float* __restrict__ Wv)
{
    extern __shared__ char smem[];
    uint32_t* Xs = reinterpret_cast<uint32_t*>(smem + PX);
    uint32_t* Ws = reinterpret_cast<uint32_t*>(smem + PW);

    const float* src; const float* W; unsigned short* dst;
    if (blockIdx.y == 0)      { src = qin; W = Wq; dst = g_Qp; }
    else if (blockIdx.y == 1) { src = kin; W = Wk; dst = g_Kp; }
    else                      { src = vin; W = Wv; dst = g_Vp; }
    const float oscale = (blockIdx.y == 0) ? SC2 : 1.0f;

    const int t = threadIdx.x, lane = t & 31, warp = t >> 5;
    const int wy = warp >> 1, wx = warp & 1;
    const int lr = lane >> 2, lc = lane & 3;

    const float4* sv = reinterpret_cast<const float4*>(src + (size_t)blockIdx.x * 8192);
    const float4* wv = reinterpret_cast<const float4*>(W);
#pragma unroll
    for (int i = 0; i < 8; i++) {
        int idx = i * 256 + t;
        float4 v = sv[idx];
        int r = idx >> 4, c = (idx & 15) * 4;
        Xs[r*68+c+0] = f2tf32(v.x); Xs[r*68+c+1] = f2tf32(v.y);
        Xs[r*68+c+2] = f2tf32(v.z); Xs[r*68+c+3] = f2tf32(v.w);
    }
#pragma unroll
    for (int i = 0; i < 4; i++) {
        int idx = i * 256 + t;
        float4 v = wv[idx];
        int r = idx >> 4, c = (idx & 15) * 4;
        Ws[r*68+c+0] = f2tf32(v.x); Ws[r*68+c+1] = f2tf32(v.y);
        Ws[r*68+c+2] = f2tf32(v.z); Ws[r*68+c+3] = f2tf32(v.w);
    }
    __syncthreads();

    float acc[2][4][4];
#pragma unroll
    for (int mt = 0; mt < 2; mt++)
#pragma unroll
        for (int nt = 0; nt < 4; nt++)
#pragma unroll
            for (int e = 0; e < 4; e++) acc[mt][nt][e] = 0.f;

#pragma unroll
    for (int kk = 0; kk < 8; kk++) {
        int k0 = kk * 8 + lc;
        uint32_t af[2][4], bf[4][2];
#pragma unroll
        for (int mt = 0; mt < 2; mt++) {
            int r = 32 * wy + 16 * mt + lr;
            af[mt][0] = Xs[r * 68 + k0];
            af[mt][1] = Xs[(r + 8) * 68 + k0];
            af[mt][2] = Xs[r * 68 + k0 + 4];
            af[mt][3] = Xs[(r + 8) * 68 + k0 + 4];
        }
#pragma unroll
        for (int nt = 0; nt < 4; nt++) {
            int nr = 32 * wx + 8 * nt + lr;
            bf[nt][0] = Ws[nr * 68 + k0];
            bf[nt][1] = Ws[nr * 68 + k0 + 4];
        }
#pragma unroll
        for (int mt = 0; mt < 2; mt++)
#pragma unroll
            for (int nt = 0; nt < 4; nt++)
                mma8(acc[mt][nt], af[mt], bf[nt]);
    }

#pragma unroll
    for (int mt = 0; mt < 2; mt++) {
#pragma unroll
        for (int half = 0; half < 2; half++) {
            int r = 32 * wy + 16 * mt + 8 * half + lr;
            int g = blockIdx.x * 128 + r;
            int n = g >> 15;
            int s = (g >> 4) & (SEQL - 1);
            int h = g & (NHEADS - 1);
            unsigned short* ob = dst + ((size_t)((n * NHEADS + h) * SEQL + s)) * HDIM;
#pragma unroll
            for (int nt = 0; nt < 4; nt++) {
                int c = 32 * wx + 8 * nt + 2 * lc;
                *reinterpret_cast<uint32_t*>(ob + c) =
                    packf16(acc[mt][nt][half * 2 + 0] * oscale,
                            acc[mt][nt][half * 2 + 1] * oscale);
            }
        }
    }
}

// ---------------------------------------------------------------------------
// 2) attention: fp16 mma, register P, f16x2 ex2 softmax (scale pre-folded
// into Q), ones-mma row sums. Block = 128 q-rows; warp owns 16 rows x all
// 64 keys. One barrier per chunk; K/V double-buffer.
// smem (ROWB=144): Qs@0, Ks0@18432 Ks1@27648, Vs0@36864 Vs1@46080,
// msk[2][64]@55296.
// ---------------------------------------------------------------------------
#define AQ   0
#define AK0  18432
#define AK1  27648
#define AV0  36864
#define AV1  46080
#define AMSK 55296
#define ATT_SMEM 55808

__global__ __launch_bounds__(256, 2) void attn_mma(const int* __restrict__ mask)
{
    extern __shared__ char smem[];
    const uint32_t sb = smem_u32(smem);
    int* msk = reinterpret_cast<int*>(smem + AMSK);

    const int tid = threadIdx.x, lane = tid & 31, warp = tid >> 5;
    const int qb = blockIdx.x, h = blockIdx.y, n = blockIdx.z;
    const int lr = lane >> 2, lc = lane & 3;
    const int lr8 = lane & 7, g1 = (lane >> 3) & 1, g2 = (lane >> 4) & 1;

    const size_t hb = ((size_t)(n * NHEADS + h)) * SEQL * HDIM;
    const unsigned short* Qg  = g_Qp + hb + (size_t)qb * 128 * 64;
    const unsigned short* Kg0 = g_Kp + hb;
    const unsigned short* Vg0 = g_Vp + hb;
    const int* mg = mask + n * SEQL;

    const uint32_t q_off = (uint32_t)((16 * warp + 8 * g1 + lr8) * ROWB + g2 * 16);
    const uint32_t k_off = (uint32_t)((8 * g2 + lr8) * ROWB + g1 * 16);
    const uint32_t v_off = (uint32_t)((8 * g1 + lr8) * ROWB + g2 * 16);

    // prologue: Q tile + chunk0 K/V + mask0, one group
#pragma unroll
    for (int i = 0; i < 4; i++) {
        int idx = i * 256 + tid;
        int r = idx >> 3, cc = idx & 7;
        CP_ASYNC16(sb + AQ + (uint32_t)(r * ROWB + cc * 16), Qg + r * 64 + cc * 8);
    }
#pragma unroll
    for (int i = 0; i < 2; i++) {
        int idx = i * 256 + tid;
        int r = idx >> 3, cc = idx & 7;
        CP_ASYNC16(sb + AK0 + (uint32_t)(r * ROWB + cc * 16), Kg0 + r * 64 + cc * 8);
        CP_ASYNC16(sb + AV0 + (uint32_t)(r * ROWB + cc * 16), Vg0 + r * 64 + cc * 8);
    }
    if (tid < 16) CP_ASYNC16(sb + AMSK + tid * 16, mg + tid * 4);
    CP_COMMIT();

    float oacc[8][4];
    float lacc[4];     // ones-mma row-sum accumulator: [0]=row lr, [2]=row lr+8
#pragma unroll
    for (int j = 0; j < 8; j++)
#pragma unroll
        for (int e = 0; e < 4; e++) oacc[j][e] = 0.f;
#pragma unroll
    for (int e = 0; e < 4; e++) lacc[e] = 0.f;
    uint32_t qa[4][4];
    const uint32_t onesb[2] = {ONEX2, ONEX2};

    for (int kb = 0; kb < SEQL / 64; kb++) {
        CP_WAIT0();
        __syncthreads();   // chunk kb visible; all warps done with old buffer

        if (kb == 0) {
#pragma unroll
            for (int ks = 0; ks < 4; ks++)
                LDSM_X4(qa[ks], sb + AQ + q_off + ks * 32);
        }
        // prefetch chunk kb+1 into the other buffer
        if (kb < SEQL / 64 - 1) {
            const unsigned short* Kg = Kg0 + (size_t)(kb + 1) * 4096;
            const unsigned short* Vg = Vg0 + (size_t)(kb + 1) * 4096;
            uint32_t kbn = sb + (((kb + 1) & 1) ? AK1 : AK0);
            uint32_t vbn = sb + (((kb + 1) & 1) ? AV1 : AV0);
#pragma unroll
            for (int i = 0; i < 2; i++) {
                int idx = i * 256 + tid;
                int r = idx >> 3, cc = idx & 7;
                CP_ASYNC16(kbn + (uint32_t)(r * ROWB + cc * 16), Kg + r * 64 + cc * 8);
                CP_ASYNC16(vbn + (uint32_t)(r * ROWB + cc * 16), Vg + r * 64 + cc * 8);
            }
            if (tid < 16)
                CP_ASYNC16(sb + AMSK + ((kb + 1) & 1) * 256 + tid * 16,
                           mg + (kb + 1) * 64 + tid * 4);
            CP_COMMIT();
        }

        const uint32_t kbase = sb + ((kb & 1) ? AK1 : AK0);
        const uint32_t vbase = sb + ((kb & 1) ? AV1 : AV0);
        const int mb = (kb & 1) * 64;

        // S_scaled = (Q*SC2) K^T
        float sacc[8][4];
#pragma unroll
        for (int j = 0; j < 8; j++)
#pragma unroll
            for (int e = 0; e < 4; e++) sacc[j][e] = 0.f;

#pragma unroll
        for (int ks = 0; ks < 4; ks++) {
            uint32_t kf[4][4];
#pragma unroll
            for (int t = 0; t < 4; t++)
                LDSM_X4(kf[t], kbase + k_off + (uint32_t)(t * 16 * ROWB) + ks * 32);
#pragma unroll
            for (int t = 0; t < 4; t++) {
                mma16(sacc[2 * t + 0], qa[ks], &kf[t][0]);
                mma16(sacc[2 * t + 1], qa[ks], &kf[t][2]);
            }
        }

        // softmax: p = 2^s_scaled via ex2.approx.f16x2; mask via f16x2 mul
        uint32_t pa[16];
#pragma unroll
        for (int t = 0; t < 8; t++) {
            int c = 8 * t + 2 * lc;
            uint32_t mm = (msk[mb + c] ? 0x3C00u : 0u)
                        | (msk[mb + c + 1] ? 0x3C000000u : 0u);
            uint32_t e01 = packf16(sacc[t][0], sacc[t][1]);
            uint32_t e23 = packf16(sacc[t][2], sacc[t][3]);
            pa[(t >> 1) * 4 + (t & 1) * 2 + 0] = hmul2(ex2h2(e01), mm);
            pa[(t >> 1) * 4 + (t & 1) * 2 + 1] = hmul2(ex2h2(e23), mm);
        }

        // O += P V ; row sums += P @ ones (one extra n=8 mma per ks)
#pragma unroll
        for (int ks = 0; ks < 4; ks++) {
            uint32_t vf[4][4];
#pragma unroll
            for (int t = 0; t < 4; t++)
                LDSM_X4T(vf[t], vbase + v_off + (uint32_t)(ks * 16 * ROWB) + t * 32);
#pragma unroll
            for (int t = 0; t < 4; t++) {
                mma16(oacc[2 * t + 0], &pa[ks * 4], &vf[t][0]);
                mma16(oacc[2 * t + 1], &pa[ks * 4], &vf[t][2]);
            }
            mma16(lacc, &pa[ks * 4], onesb);
        }
    }

    float inv0 = 1.f / lacc[0], inv1 = 1.f / lacc[2];

    // normalize + write Ao fp16
    int r0 = qb * 128 + 16 * warp + lr;
    unsigned short* b0 = g_Ao + ((size_t)(n * SEQL + r0)) * EMBED + h * HDIM;
    unsigned short* b1 = g_Ao + ((size_t)(n * SEQL + r0 + 8)) * EMBED + h * HDIM;
#pragma unroll
    for (int j = 0; j < 8; j++) {
        int c = 8 * j + 2 * lc;
        *reinterpret_cast<uint32_t*>(b0 + c) =
            packf16(oacc[j][0] * inv0, oacc[j][1] * inv0);
        *reinterpret_cast<uint32_t*>(b1 + c) =
            packf16(oacc[j][2] * inv1, oacc[j][3] * inv1);
    }
}

// ---------------------------------------------------------------------------
// 3) out = Ao @ Wo^T + bo : fp16 m16n8k16 + ldmatrix, 128x128 tile,
// k-chunk 64 DOUBLE-BUFFERED, occupancy 2 (R14 version, measured 36.4us).
// smem: As0@0 As1@18432 Bs0@36864 Bs1@55296 (128 rows x 144B each),
// bias fp32 @73728.
// ---------------------------------------------------------------------------
#define OA0 0
#define OA1 18432
#define OB0 36864
#define OB1 55296
#define OBI 73728
#define OP_SMEM 74240

__global__ __launch_bounds__(256, 2) void outproj_mma(
    const float* __restrict__ bo, float* __restrict__ out)
{
    extern __shared__ char smem[];
    const uint32_t sb = smem_u32(smem);
    float* sbo = reinterpret_cast<float*>(smem + OBI);

    const int tid = threadIdx.x, lane = tid & 31, warp = tid >> 5;
    const int wy = warp >> 1, wx = warp & 1;
    const int lr = lane >> 2, lc = lane & 3;
    const int lr8 = lane & 7, g1 = (lane >> 3) & 1, g2 = (lane >> 4) & 1;
    const int cb = blockIdx.x, rb = blockIdx.y;

    if (tid < 128) sbo[tid] = bo[cb * 128 + tid];

    const unsigned short* Ag = g_Ao + (size_t)rb * 128 * EMBED;
    const unsigned short* Bg = g_Wo16 + (size_t)cb * 128 * EMBED;

    const uint32_t a_off = (uint32_t)((32 * wy + 8 * g1 + lr8) * ROWB + g2 * 16);
    const uint32_t b_off = (uint32_t)((8 * g2 + lr8) * ROWB + g1 * 16);

    // prologue: chunk 0 into buffer 0
#pragma unroll
    for (int i = 0; i < 4; i++) {
        int idx = i * 256 + tid;
        int r = idx >> 3, cc = idx & 7;
        CP_ASYNC16(sb + OA0 + (uint32_t)(r * ROWB + cc * 16),
                   Ag + (size_t)r * EMBED + cc * 8);
        CP_ASYNC16(sb + OB0 + (uint32_t)(r * ROWB + cc * 16),
                   Bg + (size_t)r * EMBED + cc * 8);
    }
    CP_COMMIT();

    float acc[2][8][4];
#pragma unroll
    for (int mt = 0; mt < 2; mt++)
#pragma unroll
        for (int nt = 0; nt < 8; nt++)
#pragma unroll
            for (int e = 0; e < 4; e++) acc[mt][nt][e] = 0.f;

    for (int kt = 0; kt < EMBED / 64; kt++) {
        CP_WAIT0();          // chunk kt landed
        __syncthreads();     // everyone done with buffer (kt+1)&1 from kt-1

        if (kt < EMBED / 64 - 1) {       // prefetch kt+1, overlaps mma below
            int koff = (kt + 1) * 64;
            uint32_t oa = ((kt + 1) & 1) ? OA1 : OA0;
            uint32_t ob = ((kt + 1) & 1) ? OB1 : OB0;
#pragma unroll
            for (int i = 0; i < 4; i++) {
                int idx = i * 256 + tid;
                int r = idx >> 3, cc = idx & 7;
                CP_ASYNC16(sb + oa + (uint32_t)(r * ROWB + cc * 16),
                           Ag + (size_t)r * EMBED + koff + cc * 8);
                CP_ASYNC16(sb + ob + (uint32_t)(r * ROWB + cc * 16),
                           Bg + (size_t)r * EMBED + koff + cc * 8);
            }
            CP_COMMIT();
        }

        const uint32_t abase = sb + ((kt & 1) ? OA1 : OA0);
        const uint32_t bbase = sb + ((kt & 1) ? OB1 : OB0);

#pragma unroll
        for (int ks = 0; ks < 4; ks++) {
            uint32_t af[2][4], bfr[4][4];
            LDSM_X4(af[0], abase + a_off + ks * 32);
            LDSM_X4(af[1], abase + a_off + (uint32_t)(16 * ROWB) + ks * 32);
#pragma unroll
            for (int t = 0; t < 4; t++)
                LDSM_X4(bfr[t], bbase + b_off +
                               (uint32_t)((64 * wx + 16 * t) * ROWB) + ks * 32);
#pragma unroll
            for (int mt = 0; mt < 2; mt++)
#pragma unroll
                for (int t = 0; t < 4; t++) {
                    mma16(acc[mt][2 * t + 0], af[mt], &bfr[t][0]);
                    mma16(acc[mt][2 * t + 1], af[mt], &bfr[t][2]);
                }
        }
    }

#pragma unroll
    for (int mt = 0; mt < 2; mt++) {
        int r0 = 32 * wy + 16 * mt + lr, r1 = r0 + 8;
        float* o0 = out + (size_t)(rb * 128 + r0) * EMBED + cb * 128;
        float* o1 = out + (size_t)(rb * 128 + r1) * EMBED + cb * 128;
#pragma unroll
        for (int nt = 0; nt < 8; nt++) {
            int c = 64 * wx + 8 * nt + 2 * lc;
            *reinterpret_cast<float2*>(o0 + c) =
                make_float2(acc[mt][nt][0] + sbo[c], acc[mt][nt][1] + sbo[c + 1]);
            *reinterpret_cast<float2*>(o1 + c) =
                make_float2(acc[mt][nt][2] + sbo[c], acc[mt][nt][3] + sbo[c + 1]);
        }
    }
}

// ---------------------------------------------------------------------------
extern "C" void kernel_launch(void* const* d_in, const int* in_sizes, int n_in,
                              void* d_out, int out_size)
{
    (void)in_sizes; (void)n_in; (void)out_size;
    const float* vals = (const float*)d_in[0];
    const float* keys = (const float*)d_in[1];
    const float* qry  = (const float*)d_in[2];
    const int*   mask = (const int*)d_in[3];
    const float* Wv   = (const float*)d_in[4];
    const float* Wk   = (const float*)d_in[5];
    const float* Wq   = (const float*)d_in[6];
    const float* Wo   = (const float*)d_in[7];
    const float* bo   = (const float*)d_in[8];
    float* out = (float*)d_out;

    cudaFuncSetAttribute(proj_mma, cudaFuncAttributeMaxDynamicSharedMemorySize, PROJ_SMEM);
    cudaFuncSetAttribute(attn_mma, cudaFuncAttributeMaxDynamicSharedMemorySize, ATT_SMEM);
    cudaFuncSetAttribute(outproj_mma, cudaFuncAttributeMaxDynamicSharedMemorySize, OP_SMEM);

    cvt_wo<<<EMBED * EMBED / 1024, 256>>>(Wo);
    proj_mma<<<dim3(ROWS_H / 128, 3), 256, PROJ_SMEM>>>(qry, keys, vals, Wq, Wk, Wv);
    attn_mma<<<dim3(SEQL / 128, NHEADS, NBATCH), 256, ATT_SMEM>>>(mask);
    outproj_mma<<<dim3(EMBED / 128, NS / 128), 256, OP_SMEM>>>(bo, out);
}